// round 11
// baseline (speedup 1.0000x reference)
#include <cuda_runtime.h>
#include <math.h>
#include <stdint.h>

// Problem shape (fixed by the benchmark reference)
#define NB 4
#define NG 1024
#define NT 1024
#define NK 5
#define NC 8
#define HROW (NK * NC)         // 40

// Tiling: 16 t-lanes x 8 channels = 128 threads; each thread owns 4 t's.
#define BLOCK 128
#define TL 16                  // t-lanes
#define T_TILE 64              // 4 t's per lane * 16 lanes
#define N_TTILES 16            // 16 * 64 = 1024 exactly
#define G_SPLIT 16
#define GH (NG / G_SPLIT)      // 64 g's staged per CTA

// smem: uw (float2 per (g,c)) + h duplicated as float2 {h,h}
#define UW_F (2 * GH * NC)         // 1024 floats (4KB)
#define HH_F (2 * GH * HROW)       // 5120 floats (20KB)
#define SMEM_BYTES ((UW_F + HH_F) * 4)   // 24576 B -> 7 CTAs/SM still fits

#define NEG_HALF_LOG2E -0.72134752044448170f   // -0.5 * log2(e)

__device__ __forceinline__ float ex2f(float x) {
    float r; asm("ex2.approx.ftz.f32 %0, %1;" : "=f"(r) : "f"(x)); return r;
}
__device__ __forceinline__ uint64_t pack2(float lo, float hi) {
    uint64_t r; asm("mov.b64 %0, {%1, %2};" : "=l"(r) : "f"(lo), "f"(hi)); return r;
}
__device__ __forceinline__ void unpack2(uint64_t v, float& lo, float& hi) {
    asm("mov.b64 {%0, %1}, %2;" : "=f"(lo), "=f"(hi) : "l"(v));
}
__device__ __forceinline__ uint64_t fma2(uint64_t a, uint64_t b, uint64_t c) {
    uint64_t d;
    asm("fma.rn.f32x2 %0, %1, %2, %3;" : "=l"(d) : "l"(a), "l"(b), "l"(c));
    return d;
}

__global__ __launch_bounds__(BLOCK) void gauss_kernel(
    const float* __restrict__ x_grid,   // (b, g, c)
    const float* __restrict__ h_grid,   // (b, g, k, c)
    const float* __restrict__ target_x, // (b, t, c)
    const float* __restrict__ sigma,    // (k, c)
    float* __restrict__ out)            // (b, t, k, c)
{
    extern __shared__ float sm[];
    float* uw = sm;             // float2[(g,c)] = {u = m0*x^2, w = -2*m0*x}
    float* hh = uw + UW_F;      // float2[(g,k,c)] = {h, h}  (duplicated for f32x2)

    const int gh   = blockIdx.x;    // g slice
    const int tile = blockIdx.y;    // t tile
    const int b    = blockIdx.z;    // batch
    const int tid  = threadIdx.x;
    const int c    = tid & (NC - 1);
    const int tl   = tid >> 3;

    // Per-channel exponent multipliers from sigma (base-2; matches exp(sigma)+EPS)
    float mk[NK];
    bool uni = true;
    #pragma unroll
    for (int k = 0; k < NK; ++k) {
        float s = expf(sigma[k * NC + c]) + 1e-6f;
        mk[k] = NEG_HALF_LOG2E / (s * s);
        if (k > 0) uni = uni && (mk[k] == mk[0]);
    }
    const float m0 = mk[0];

    // ---- Stage x -> (u, w). BLOCK % NC == 0 so (tid + r*BLOCK) & 7 == c always.
    {
        const float* xg = x_grid + ((size_t)b * NG + (size_t)gh * GH) * NC;
        #pragma unroll
        for (int r = 0; r < GH * NC / BLOCK; ++r) {       // 4 exact iters
            int i = tid + r * BLOCK;
            float x = xg[i];
            *(float2*)(uw + 2 * i) = make_float2(m0 * x * x, -2.0f * m0 * x);
        }
    }
    // ---- Stage h duplicated: read float2, write float4 {x,x,y,y}. No index math.
    {
        const float2* hg2 = (const float2*)(h_grid + ((size_t)b * NG + (size_t)gh * GH) * HROW);
        float4* hh4 = (float4*)hh;
        #pragma unroll
        for (int r = 0; r < GH * HROW / 2 / BLOCK; ++r) { // 10 exact iters
            int i = tid + r * BLOCK;
            float2 v = hg2[i];
            hh4[i] = make_float4(v.x, v.x, v.y, v.y);
        }
    }
    __syncthreads();

    // 4 t's per thread: t = tile*64 + tl + {0,16,32,48}; always < 1024.
    const int tbase = tile * T_TILE + tl;
    const float* ty = target_x + ((size_t)b * NT + tbase) * NC + c;
    const float y0 = ty[0 * TL * NC];
    const float y1 = ty[1 * TL * NC];
    const float y2 = ty[2 * TL * NC];
    const float y3 = ty[3 * TL * NC];

    const float2* uwc = (const float2*)uw + c;
    const float2* hhc = (const float2*)hh + c;   // float2-element index: g*HROW + k*NC + c

    if (uni) {
        // Fast path: 1 ex2 per (g,t); packed f32x2 FMA over t-pairs; h pre-duplicated.
        uint64_t accA[NK] = {0, 0, 0, 0, 0};     // {sum_t0, sum_t1}
        uint64_t accB[NK] = {0, 0, 0, 0, 0};     // {sum_t2, sum_t3}
        #pragma unroll 2
        for (int g = 0; g < GH; ++g) {
            float2 p = uwc[g * NC];
            float e0 = ex2f(fmaf(p.y, y0, p.x));
            float e1 = ex2f(fmaf(p.y, y1, p.x));
            float e2 = ex2f(fmaf(p.y, y2, p.x));
            float e3 = ex2f(fmaf(p.y, y3, p.x));
            uint64_t e01 = pack2(e0, e1);
            uint64_t e23 = pack2(e2, e3);
            const float2* hp = hhc + g * HROW;
            #pragma unroll
            for (int k = 0; k < NK; ++k) {
                uint64_t hv = *(const uint64_t*)(hp + k * NC);   // LDS.64 {h,h}
                accA[k] = fma2(e01, hv, accA[k]);
                accB[k] = fma2(e23, hv, accB[k]);
            }
        }
        const float s0 = ex2f(m0 * y0 * y0);
        const float s1 = ex2f(m0 * y1 * y1);
        const float s2 = ex2f(m0 * y2 * y2);
        const float s3 = ex2f(m0 * y3 * y3);
        float* o = out + ((size_t)b * NT + tbase) * HROW + c;
        #pragma unroll
        for (int k = 0; k < NK; ++k) {
            float vA0, vA1, vB0, vB1;
            unpack2(accA[k], vA0, vA1);
            unpack2(accB[k], vB0, vB1);
            atomicAdd(o + 0 * TL * HROW + k * NC, vA0 * s0);
            atomicAdd(o + 1 * TL * HROW + k * NC, vA1 * s1);
            atomicAdd(o + 2 * TL * HROW + k * NC, vB0 * s2);
            atomicAdd(o + 3 * TL * HROW + k * NC, vB1 * s3);
        }
    } else {
        // General path: per-k scales, scalar math (reads lo half of duplicated h).
        float a0[NK] = {0,0,0,0,0};
        float a1[NK] = {0,0,0,0,0};
        float a2[NK] = {0,0,0,0,0};
        float a3[NK] = {0,0,0,0,0};
        float rk[NK];
        #pragma unroll
        for (int k = 0; k < NK; ++k) rk[k] = mk[k] / m0;
        const float r0 = m0 * y0 * y0;
        const float r1 = m0 * y1 * y1;
        const float r2 = m0 * y2 * y2;
        const float r3 = m0 * y3 * y3;
        for (int g = 0; g < GH; ++g) {
            float2 p = uwc[g * NC];
            float q0 = fmaf(p.y, y0, p.x) + r0;
            float q1 = fmaf(p.y, y1, p.x) + r1;
            float q2 = fmaf(p.y, y2, p.x) + r2;
            float q3 = fmaf(p.y, y3, p.x) + r3;
            const float* hp = (const float*)(hhc + g * HROW);
            #pragma unroll
            for (int k = 0; k < NK; ++k) {
                float h = hp[2 * k * NC];
                a0[k] = fmaf(ex2f(q0 * rk[k]), h, a0[k]);
                a1[k] = fmaf(ex2f(q1 * rk[k]), h, a1[k]);
                a2[k] = fmaf(ex2f(q2 * rk[k]), h, a2[k]);
                a3[k] = fmaf(ex2f(q3 * rk[k]), h, a3[k]);
            }
        }
        float* o = out + ((size_t)b * NT + tbase) * HROW + c;
        #pragma unroll
        for (int k = 0; k < NK; ++k) {
            atomicAdd(o + 0 * TL * HROW + k * NC, a0[k]);
            atomicAdd(o + 1 * TL * HROW + k * NC, a1[k]);
            atomicAdd(o + 2 * TL * HROW + k * NC, a2[k]);
            atomicAdd(o + 3 * TL * HROW + k * NC, a3[k]);
        }
    }
}

extern "C" void kernel_launch(void* const* d_in, const int* in_sizes, int n_in,
                              void* d_out, int out_size) {
    const float* x_grid  = (const float*)d_in[0];
    const float* h_grid  = (const float*)d_in[1];
    const float* target  = (const float*)d_in[2];
    const float* sigma   = (const float*)d_in[3];
    float* out = (float*)d_out;

    cudaFuncSetAttribute(gauss_kernel, cudaFuncAttributeMaxDynamicSharedMemorySize, SMEM_BYTES);

    cudaMemsetAsync(out, 0, (size_t)out_size * sizeof(float), 0);

    dim3 grid(G_SPLIT, N_TTILES, NB);   // 16 x 16 x 4 = 1024 CTAs, ~7/SM, 28 warps/SM
    gauss_kernel<<<grid, BLOCK, SMEM_BYTES>>>(x_grid, h_grid, target, sigma, out);
}

// round 14
// speedup vs baseline: 1.1361x; 1.1361x over previous
#include <cuda_runtime.h>
#include <math.h>
#include <stdint.h>

// Problem shape (fixed by the benchmark reference)
#define NB 4
#define NG 1024
#define NT 1024
#define NK 5
#define NC 8
#define HROW (NK * NC)         // 40

// Tiling: 16 t-lanes x 8 channels = 128 threads; each thread owns 4 t's.
#define BLOCK 128
#define TL 16
#define T_TILE 64              // 4 t's per lane * 16 lanes
#define N_TTILES 16            // 16 * 64 = 1024 exactly
#define G_SPLIT 16
#define GH (NG / G_SPLIT)      // 64 g's staged per CTA

// smem layouts:
//  uwT: float2 [NC][66]  ([c][g], stride 66 -> LDS.128 aligned + conflict-free)
//  hT : float  [GH][NC][12] (k-contiguous, stride 12 -> LDS.128 conflict-free)
#define UWT_STRIDE 66
#define UWT_F2 (NC * UWT_STRIDE)          // 528 float2 = 4224 B
#define HT_W 12
#define HT_F (GH * NC * HT_W)             // 6144 floats = 24576 B
#define SMEM_BYTES (UWT_F2 * 8 + HT_F * 4)   // 28800 B -> 7 CTAs/SM fits

#define NEG_HALF_LOG2E -0.72134752044448170f   // -0.5 * log2(e)

__device__ __forceinline__ float ex2f(float x) {
    float r; asm("ex2.approx.ftz.f32 %0, %1;" : "=f"(r) : "f"(x)); return r;
}
__device__ __forceinline__ uint64_t pack2(float lo, float hi) {
    uint64_t r; asm("mov.b64 %0, {%1, %2};" : "=l"(r) : "f"(lo), "f"(hi)); return r;
}
__device__ __forceinline__ void unpack2(uint64_t v, float& lo, float& hi) {
    asm("mov.b64 {%0, %1}, %2;" : "=f"(lo), "=f"(hi) : "l"(v));
}
__device__ __forceinline__ uint64_t fma2(uint64_t a, uint64_t b, uint64_t c) {
    uint64_t d;
    asm("fma.rn.f32x2 %0, %1, %2, %3;" : "=l"(d) : "l"(a), "l"(b), "l"(c));
    return d;
}

__global__ __launch_bounds__(BLOCK) void gauss_kernel(
    const float* __restrict__ x_grid,   // (b, g, c)
    const float* __restrict__ h_grid,   // (b, g, k, c)
    const float* __restrict__ target_x, // (b, t, c)
    const float* __restrict__ sigma,    // (k, c)
    float* __restrict__ out)            // (b, t, k, c)
{
    extern __shared__ float sm[];
    float2* uwT = (float2*)sm;          // [c][g]: {u = m0*x^2, w = -2*m0*x}
    float*  hT  = sm + UWT_F2 * 2;      // [g][c][12]: {k0..k4, pad...}

    const int gh   = blockIdx.x;
    const int tile = blockIdx.y;
    const int b    = blockIdx.z;
    const int tid  = threadIdx.x;
    const int c    = tid & (NC - 1);
    const int tl   = tid >> 3;

    // Per-channel exponent multipliers from sigma (base-2; matches exp(sigma)+EPS)
    float mk[NK];
    bool uni = true;
    #pragma unroll
    for (int k = 0; k < NK; ++k) {
        float s = expf(sigma[k * NC + c]) + 1e-6f;
        mk[k] = NEG_HALF_LOG2E / (s * s);
        if (k > 0) uni = uni && (mk[k] == mk[0]);
    }
    const float m0 = mk[0];

    // ---- Stage x -> uwT[c][g]. (tid + r*BLOCK) & 7 == c so m0 matches the channel.
    {
        const float* xg = x_grid + ((size_t)b * NG + (size_t)gh * GH) * NC;
        #pragma unroll
        for (int r = 0; r < GH * NC / BLOCK; ++r) {       // 4 exact iters
            int i = tid + r * BLOCK;
            int g  = i >> 3;
            int cc = i & 7;
            float x = xg[i];
            uwT[cc * UWT_STRIDE + g] = make_float2(m0 * x * x, -2.0f * m0 * x);
        }
    }
    // ---- Stage h -> hT[g][c][12] (k-contiguous). Shift/mask indexing only.
    {
        const float* hg = h_grid + ((size_t)b * NG + (size_t)gh * GH) * HROW;
        #pragma unroll
        for (int r = 0; r < GH * NC / BLOCK; ++r) {       // 4 exact iters
            int i = tid + r * BLOCK;
            int g  = i >> 3;
            int cc = i & 7;
            const float* src = hg + g * HROW + cc;
            float k0 = src[0 * NC], k1 = src[1 * NC], k2 = src[2 * NC],
                  k3 = src[3 * NC], k4 = src[4 * NC];
            float* dst = hT + g * (NC * HT_W) + cc * HT_W;
            *(float4*)dst = make_float4(k0, k1, k2, k3);
            dst[4] = k4;
        }
    }
    __syncthreads();

    // 4 t's per thread: t = tile*64 + tl + {0,16,32,48}; always < 1024.
    const int tbase = tile * T_TILE + tl;
    const float* ty = target_x + ((size_t)b * NT + tbase) * NC + c;
    float y[4];
    #pragma unroll
    for (int j = 0; j < 4; ++j) y[j] = ty[j * TL * NC];

    const float2* uwrow = uwT + c * UWT_STRIDE;   // [g]
    const float*  hrow  = hT + c * HT_W;          // + g*(NC*HT_W)

    if (uni) {
        // Fast path: 1 ex2 per (g,t); f32x2 FMA over k-pairs taken straight from LDS.128
        // (no h duplication, no h packing); 2^(m0*y^2) factored out of the g-sum.
        uint64_t pA[4] = {0, 0, 0, 0};   // {k0,k1} sums per t
        uint64_t pB[4] = {0, 0, 0, 0};   // {k2,k3} sums per t
        float    c4[4] = {0, 0, 0, 0};   // k4 sums per t

        for (int g = 0; g < GH; g += 2) {
            float4 uwp = *(const float4*)(uwrow + g);   // u_g, w_g, u_g1, w_g1
            #pragma unroll
            for (int s = 0; s < 2; ++s) {
                const float u = s ? uwp.z : uwp.x;
                const float w = s ? uwp.w : uwp.y;
                const float* hp = hrow + (g + s) * (NC * HT_W);
                ulonglong2 hq = *(const ulonglong2*)hp;     // LDS.128: {k0,k1},{k2,k3}
                float h4 = hp[4];
                #pragma unroll
                for (int j = 0; j < 4; ++j) {
                    float e = ex2f(fmaf(w, y[j], u));
                    uint64_t ee = pack2(e, e);
                    pA[j] = fma2(ee, hq.x, pA[j]);
                    pB[j] = fma2(ee, hq.y, pB[j]);
                    c4[j] = fmaf(e, h4, c4[j]);
                }
            }
        }
        float* o = out + ((size_t)b * NT + tbase) * HROW + c;
        #pragma unroll
        for (int j = 0; j < 4; ++j) {
            const float s = ex2f(m0 * y[j] * y[j]);
            float v0, v1;
            float* oj = o + j * TL * HROW;
            unpack2(pA[j], v0, v1);
            atomicAdd(oj + 0 * NC, v0 * s);
            atomicAdd(oj + 1 * NC, v1 * s);
            unpack2(pB[j], v0, v1);
            atomicAdd(oj + 2 * NC, v0 * s);
            atomicAdd(oj + 3 * NC, v1 * s);
            atomicAdd(oj + 4 * NC, c4[j] * s);
        }
    } else {
        // General path: per-k scales, scalar math on the k-contiguous layout.
        float acc[4][NK] = {};
        float rk[NK];
        #pragma unroll
        for (int k = 0; k < NK; ++k) rk[k] = mk[k] / m0;
        float ry[4];
        #pragma unroll
        for (int j = 0; j < 4; ++j) ry[j] = m0 * y[j] * y[j];
        for (int g = 0; g < GH; ++g) {
            float2 p = uwrow[g];
            const float* hp = hrow + g * (NC * HT_W);
            #pragma unroll
            for (int j = 0; j < 4; ++j) {
                float q = fmaf(p.y, y[j], p.x) + ry[j];
                #pragma unroll
                for (int k = 0; k < NK; ++k)
                    acc[j][k] = fmaf(ex2f(q * rk[k]), hp[k], acc[j][k]);
            }
        }
        float* o = out + ((size_t)b * NT + tbase) * HROW + c;
        #pragma unroll
        for (int j = 0; j < 4; ++j)
            #pragma unroll
            for (int k = 0; k < NK; ++k)
                atomicAdd(o + j * TL * HROW + k * NC, acc[j][k]);
    }
}

extern "C" void kernel_launch(void* const* d_in, const int* in_sizes, int n_in,
                              void* d_out, int out_size) {
    const float* x_grid  = (const float*)d_in[0];
    const float* h_grid  = (const float*)d_in[1];
    const float* target  = (const float*)d_in[2];
    const float* sigma   = (const float*)d_in[3];
    float* out = (float*)d_out;

    cudaFuncSetAttribute(gauss_kernel, cudaFuncAttributeMaxDynamicSharedMemorySize, SMEM_BYTES);

    cudaMemsetAsync(out, 0, (size_t)out_size * sizeof(float), 0);

    dim3 grid(G_SPLIT, N_TTILES, NB);   // 16 x 16 x 4 = 1024 CTAs, 7/SM, 28 warps/SM
    gauss_kernel<<<grid, BLOCK, SMEM_BYTES>>>(x_grid, h_grid, target, sigma, out);
}